// round 7
// baseline (speedup 1.0000x reference)
#include <cuda_runtime.h>
#include <cuda_bf16.h>
#include <mma.h>
#include <cstdint>

using namespace nvcuda;

// ---------------- Problem dims ----------------
#define M_REAL 200            // T*C rows
#define M_PAD 256             // padded to 16 m16 tiles
#define KK 16384              // H*W
#define NN 8192               // D
#define DTILE 128             // d columns per CTA
#define KSPLIT 2
#define KPER (KK / KSPLIT)    // 8192
#define K_CHUNK 64
#define NCH (KPER / K_CHUNK)  // 128
#define NTHREADS 256

// ---------------- smem layout (bytes) ----------------
// A tile per buffer: 2 limbs * 256 rows * 72 bf16 (pitch 144B) = 73728 B
// B tile per buffer: 128 d-rows * 72 bf16 (pitch 144B)         = 18432 B
// B fp32 staging   : 64 k * 128 d * 4B                          = 32768 B
#define APITCH 72
#define BPITCH 72
#define SMA_BUF 73728
#define SMB_BUF 18432
#define SM_A 0
#define SM_B (2 * SMA_BUF)              // 147456
#define SM_STG (SM_B + 2 * SMB_BUF)     // 184320
#define SMEM_TOTAL (SM_STG + 32768)     // 217088

// ---------------- device scratch (no runtime allocation) ----------------
__device__ __nv_bfloat16 g_Ahi[M_PAD * KK];
__device__ __nv_bfloat16 g_Alo[M_PAD * KK];
__device__ float g_scr[NN];

// ---------------- kernel 1: hist fp32 -> split bf16 (hi+lo), zero-pad, zero g_scr ----------------
__global__ void st_convert(const float* __restrict__ hist) {
    int idx = blockIdx.x * blockDim.x + threadIdx.x;   // 0 .. M_PAD*KK/4-1
    if (idx < NN) g_scr[idx] = 0.0f;
    int base = idx << 2;
    __nv_bfloat162 h0, h1, l0, l1;
    if (idx < (M_REAL * KK) / 4) {
        float4 h = *(const float4*)(hist + base);
        __nv_bfloat16 a0 = __float2bfloat16_rn(h.x);
        __nv_bfloat16 a1 = __float2bfloat16_rn(h.y);
        __nv_bfloat16 a2 = __float2bfloat16_rn(h.z);
        __nv_bfloat16 a3 = __float2bfloat16_rn(h.w);
        h0 = __halves2bfloat162(a0, a1);
        h1 = __halves2bfloat162(a2, a3);
        l0 = __halves2bfloat162(__float2bfloat16_rn(h.x - __bfloat162float(a0)),
                                __float2bfloat16_rn(h.y - __bfloat162float(a1)));
        l1 = __halves2bfloat162(__float2bfloat16_rn(h.z - __bfloat162float(a2)),
                                __float2bfloat16_rn(h.w - __bfloat162float(a3)));
    } else {
        __nv_bfloat16 z = __float2bfloat16_rn(0.0f);
        h0 = h1 = l0 = l1 = __halves2bfloat162(z, z);
    }
    *(__nv_bfloat162*)(g_Ahi + base)     = h0;
    *(__nv_bfloat162*)(g_Ahi + base + 2) = h1;
    *(__nv_bfloat162*)(g_Alo + base)     = l0;
    *(__nv_bfloat162*)(g_Alo + base + 2) = l1;
}

// ---------------- kernel 2: WMMA bf16 GEMM + fused weighted-sum epilogue ----------------
__global__ void __launch_bounds__(NTHREADS, 1)
st_gemm(const float* __restrict__ pos_w,
        const float* __restrict__ time_w,
        const float* __restrict__ pol_w)
{
    extern __shared__ char smem[];
    const uint32_t sbase = (uint32_t)__cvta_generic_to_shared(smem);
    const int tid = threadIdx.x;
    const int w = tid >> 5;
    const int d0 = blockIdx.x * DTILE;
    const int kb0 = blockIdx.y * KPER;

    wmma::fragment<wmma::accumulator, 16, 16, 16, float> acc[2][8];
    #pragma unroll
    for (int mt = 0; mt < 2; mt++)
        #pragma unroll
        for (int nf = 0; nf < 8; nf++)
            wmma::fill_fragment(acc[mt][nf], 0.0f);

    // ---- async loaders ----
    auto load_async = [&](int c, int buf) {
        const int kb = kb0 + c * K_CHUNK;
        // A: 512 rows (limb-major) x 128 B of bf16, into pitch-144 smem
        {
            uint32_t abase = sbase + SM_A + (uint32_t)buf * SMA_BUF;
            const int unit = tid & 7, r0 = tid >> 3;
            #pragma unroll
            for (int i = 0; i < 16; i++) {
                int r = r0 + i * 32;              // 0..511
                int limb = r >> 8, m = r & 255;
                const __nv_bfloat16* src =
                    (limb ? g_Alo : g_Ahi) + m * KK + kb + unit * 8;
                uint32_t dst = abase + (uint32_t)(r * 144 + unit * 16);
                asm volatile("cp.async.cg.shared.global [%0], [%1], 16;"
                             :: "r"(dst), "l"(src) : "memory");
            }
        }
        // B staging: 64 k-rows x 512 B fp32
        {
            uint32_t stg = sbase + SM_STG;
            const int bu = tid & 31, kr0 = tid >> 5;
            #pragma unroll
            for (int i = 0; i < 8; i++) {
                int k = kr0 + i * 8;
                const float* src = pos_w + (size_t)(kb + k) * NN + d0 + bu * 4;
                uint32_t dst = stg + (uint32_t)(k * 512 + bu * 16);
                asm volatile("cp.async.cg.shared.global [%0], [%1], 16;"
                             :: "r"(dst), "l"(src) : "memory");
            }
        }
        asm volatile("cp.async.commit_group;" ::: "memory");
    };

    // fp32 staging -> bf16 col-major B tile ([d][k], pitch 72)
    auto convertB = [&](int buf) {
        const float* stg = (const float*)(smem + SM_STG);
        __nv_bfloat16* smB = (__nv_bfloat16*)(smem + SM_B + buf * SMB_BUF);
        const int d = tid & 127, kh = tid >> 7;
        #pragma unroll
        for (int j = 0; j < 16; j++) {
            int k = kh * 32 + 2 * j;
            float f0 = stg[k * DTILE + d];
            float f1 = stg[(k + 1) * DTILE + d];
            *(__nv_bfloat162*)(smB + d * BPITCH + k) = __floats2bfloat162_rn(f0, f1);
        }
    };

    auto compute = [&](int buf) {
        const __nv_bfloat16* smA = (const __nv_bfloat16*)(smem + SM_A + buf * SMA_BUF);
        const __nv_bfloat16* smB = (const __nv_bfloat16*)(smem + SM_B + buf * SMB_BUF);
        #pragma unroll
        for (int kt = 0; kt < 4; kt++) {
            wmma::fragment<wmma::matrix_b, 16, 16, 16, __nv_bfloat16, wmma::col_major> bfrag[8];
            #pragma unroll
            for (int nf = 0; nf < 8; nf++)
                wmma::load_matrix_sync(bfrag[nf], smB + nf * 16 * BPITCH + kt * 16, BPITCH);
            #pragma unroll
            for (int limb = 0; limb < 2; limb++) {
                #pragma unroll
                for (int mt = 0; mt < 2; mt++) {
                    wmma::fragment<wmma::matrix_a, 16, 16, 16, __nv_bfloat16, wmma::row_major> afrag;
                    wmma::load_matrix_sync(
                        afrag, smA + (limb * M_PAD + (w * 2 + mt) * 16) * APITCH + kt * 16,
                        APITCH);
                    #pragma unroll
                    for (int nf = 0; nf < 8; nf++)
                        wmma::mma_sync(acc[mt][nf], afrag, bfrag[nf], acc[mt][nf]);
                }
            }
        }
    };

    // ---- pipelined mainloop ----
    load_async(0, 0);
    asm volatile("cp.async.wait_group 0;" ::: "memory");
    __syncthreads();
    convertB(0);
    __syncthreads();

    for (int c = 0; c < NCH; c++) {
        const int buf = c & 1;
        if (c + 1 < NCH) load_async(c + 1, buf ^ 1);
        compute(buf);
        if (c + 1 < NCH) {
            asm volatile("cp.async.wait_group 0;" ::: "memory");
            __syncthreads();
            convertB(buf ^ 1);
        }
        __syncthreads();
    }

    // ---- epilogue: C -> smem, weighted reduce over m, 2 deterministic atomics per d ----
    float* smC = (float*)(smem + SM_A);   // 256 x 128 fp32 = 128 KB, reuse A buffers
    #pragma unroll
    for (int mt = 0; mt < 2; mt++)
        #pragma unroll
        for (int nf = 0; nf < 8; nf++)
            wmma::store_matrix_sync(smC + (w * 32 + mt * 16) * DTILE + nf * 16,
                                    acc[mt][nf], DTILE, wmma::mem_row_major);
    __syncthreads();

    const int d = tid & 127, half = tid >> 7;
    const int m0 = half * 128;
    const int m1 = half ? M_REAL : 128;
    float s = 0.0f;
    for (int m = m0; m < m1; m++) {
        float wv = time_w[(size_t)(m >> 1) * NN + d0 + d] *
                   pol_w[(size_t)(m & 1) * NN + d0 + d];
        s += smC[m * DTILE + d] * wv;
    }
    float* red = (float*)(smem + SM_STG);
    red[tid] = s;
    __syncthreads();
    if (tid < DTILE)
        atomicAdd(&g_scr[d0 + tid], red[tid] + red[tid + DTILE]);
}

// ---------------- kernel 3: sign ----------------
__global__ void st_sign(float* __restrict__ out) {
    int i = blockIdx.x * blockDim.x + threadIdx.x;
    float v = g_scr[i];
    out[i] = (v > 0.0f) ? 1.0f : ((v < 0.0f) ? -1.0f : 0.0f);
}

// ---------------- launch ----------------
extern "C" void kernel_launch(void* const* d_in, const int* in_sizes, int n_in,
                              void* d_out, int out_size) {
    const float* hist   = (const float*)d_in[0];   // [100, 2, 128, 128]
    const float* time_w = (const float*)d_in[1];   // [100, 8192]
    const float* pol_w  = (const float*)d_in[2];   // [2, 8192]
    const float* pos_w  = (const float*)d_in[3];   // [16384, 8192]
    float* out = (float*)d_out;                    // [8192]

    cudaFuncSetAttribute(st_gemm, cudaFuncAttributeMaxDynamicSharedMemorySize, SMEM_TOTAL);

    st_convert<<<(M_PAD * KK / 4) / 256, 256>>>(hist);
    dim3 grid(NN / DTILE, KSPLIT);   // (64, 2) = 128 CTAs, one wave
    st_gemm<<<grid, NTHREADS, SMEM_TOTAL>>>(pos_w, time_w, pol_w);
    st_sign<<<NN / 256, 256>>>(out);
}